// round 11
// baseline (speedup 1.0000x reference)
#include <cuda_runtime.h>

// Problem constants
#define TABN    1024            // table intervals over [-16, 16], h = 2^-5
#define NSTEP   32
#define NPATH   65536
#define DTC     0.03125f
#define MU_CF   0.05f
#define SIG_CF  0.2f
#define CDT     0.0015625f      // DTC * MU_CF
#define CDT2    (CDT * CDT)

#define PB_TPB    64
#define PB_BLOCKS (NPATH / PB_TPB)   // 1024

#define BK_TPB    576                // 9 points x 64 neurons
#define BK_BLOCKS (TABN / 8)         // 128 blocks x 8 intervals

// Scratch (static device globals; no runtime allocation)
__device__ float4   g_tab[TABN];          // (y_i, dy_i, tanh_i, dtanh_i)
__device__ float2   g_part[PB_BLOCKS];    // per-block (sum ycv^2, sum yT^2)
__device__ unsigned g_ctr = 0;            // last-block ticket (reset by build)

// ---------------------------------------------------------------------------
// Kernel 1: build the y(x)/tanh(x) slope table (net at t=0 is scalar in x).
// Block = 576 threads = 9 overlapping table points x 64 output neurons, so
// each block writes 8 complete (value, slope) entries with no cross-block dep.
// Also resets the reduction ticket counter for this graph replay.
// ---------------------------------------------------------------------------
__global__ __launch_bounds__(BK_TPB) void build_kernel(
    const float* __restrict__ W1, const float* __restrict__ b1,
    const float* __restrict__ W2, const float* __restrict__ b2,
    const float* __restrict__ W3, const float* __restrict__ b3)
{
    __shared__ float sW2[64 * 64];   // 16 KB
    __shared__ float sh1[9 * 64];
    __shared__ float sred[18];
    __shared__ float sY[9];

    const int tid = threadIdx.x;
    if (blockIdx.x == 0 && tid == 0) g_ctr = 0;   // reset ticket each replay

    // Stage W2 into shared memory (coalesced float4)
    {
        const float4* src = (const float4*)W2;
        float4* dst = (float4*)sW2;
        for (int i = tid; i < 1024; i += BK_TPB) dst[i] = src[i];
    }

    const int p  = tid >> 6;                 // local point 0..8
    const int j  = tid & 63;                 // output neuron 0..63
    const int pt = blockIdx.x * 8 + p;       // global table point 0..TABN
    const float h = 32.0f / (float)TABN;
    const float x = -16.0f + (float)pt * h;

    // h1_j for this point, shared within the point group
    sh1[tid] = tanhf(fmaf(x, W1[64 + j], b1[j]));
    __syncthreads();

    // a_j = b2_j + sum_k h1_k * W2[k][j]
    float a = b2[j];
    #pragma unroll
    for (int k = 0; k < 64; k++)
        a = fmaf(sh1[p * 64 + k], sW2[k * 64 + j], a);

    float contrib = tanhf(a) * W3[2 * j];

    #pragma unroll
    for (int off = 16; off > 0; off >>= 1)
        contrib += __shfl_xor_sync(0xFFFFFFFFu, contrib, off);
    if ((tid & 31) == 0) sred[tid >> 5] = contrib;
    __syncthreads();

    if (tid < 9) sY[tid] = sred[2 * tid] + sred[2 * tid + 1] + b3[0];
    __syncthreads();

    if (tid < 8) {
        const int i = blockIdx.x * 8 + tid;
        const float xi = -16.0f + (float)i * h;
        const float y0 = sY[tid], y1 = sY[tid + 1];
        const float t0 = tanhf(xi), t1 = tanhf(xi + h);
        g_tab[i] = make_float4(y0, y1 - y0, t0, t1 - t0);
    }
}

// ---------------------------------------------------------------------------
// Kernel 2: one thread per path, 32 tamed-Euler steps, fused final reduction.
// dW tile (64 paths x 32 steps) is staged through smem with fully-coalesced
// float4 global loads, stored at row stride 33 -> conflict-free scalar LDS.
// First-order tamed drift (e^2 correction = CDT^3 x^2 <= 2e-7/step, dropped):
//   x *= (1+CDT) + SIG*dw - CDT^2*|x|
// ---------------------------------------------------------------------------
__global__ __launch_bounds__(PB_TPB) void path_kernel(
    const float* __restrict__ x0, const float* __restrict__ dW,
    float* __restrict__ out)
{
    __shared__ float sdw[PB_TPB * 33];       // 8448 B, stride 33 kills conflicts
    const int tid = threadIdx.x;
    const int b   = blockIdx.x * PB_TPB + tid;
    const float4* __restrict__ tab = g_tab;

    // Coalesced staging of this block's dW tile (64 x 32 floats = 512 float4)
    {
        const float4* g = (const float4*)dW + (size_t)blockIdx.x * (PB_TPB * 8);
        #pragma unroll
        for (int k = 0; k < 8; k++) {
            const int c = tid + PB_TPB * k;   // consecutive across lanes
            const float4 v = __ldg(&g[c]);
            const int r = c >> 3, j = c & 7;
            float* dst = &sdw[r * 33 + j * 4];
            dst[0] = v.x; dst[1] = v.y; dst[2] = v.z; dst[3] = v.w;
        }
    }
    float x = __ldg(&x0[b]);
    __syncthreads();

    float ylin = 1.0f;
    float acc  = 0.0f;
    const float* __restrict__ mydw = &sdw[tid * 33];

    #pragma unroll
    for (int s = 0; s < NSTEP; s++) {
        const float dw = mydw[s];

        // table lookup: u = (x + 16) * 32
        float u = fmaf(x, 32.0f, 512.0f);
        u = fminf(fmaxf(u, 0.0f), 1023.999f);
        const int   i = (int)u;
        const float f = u - (float)i;
        const float4 e = __ldg(&tab[i]);
        const float y  = fmaf(f, e.y, e.x);   // y(x)
        const float th = fmaf(f, e.w, e.z);   // tanh(x)

        const float ycv = y - ylin;
        acc  = fmaf(ycv, ycv, acc);
        ylin = fmaf(-DTC, th, ylin);

        const float a = fmaf(SIG_CF, dw, 1.0f + CDT);   // off the x-chain
        x *= (a - CDT2 * fabsf(x));                     // 12-cycle serial chain
    }

    float yT2 = ylin * ylin;

    // Deterministic block reduction (2 warps)
    #pragma unroll
    for (int off = 16; off > 0; off >>= 1) {
        acc += __shfl_xor_sync(0xFFFFFFFFu, acc, off);
        yT2 += __shfl_xor_sync(0xFFFFFFFFu, yT2, off);
    }
    __shared__ float2 sp[PB_TPB / 32];
    __shared__ bool   s_last;
    if ((tid & 31) == 0) sp[tid >> 5] = make_float2(acc, yT2);
    __syncthreads();
    if (tid == 0) {
        g_part[blockIdx.x] = make_float2(sp[0].x + sp[1].x, sp[0].y + sp[1].y);
        __threadfence();
        const unsigned t = atomicAdd(&g_ctr, 1u);
        s_last = (t == PB_BLOCKS - 1);
    }
    __syncthreads();

    // Last block performs the deterministic final reduction (fixed order).
    if (s_last) {
        __threadfence();
        double a1 = 0.0, a2 = 0.0;
        #pragma unroll 4
        for (int k = tid; k < PB_BLOCKS; k += PB_TPB) {
            const float2 p = g_part[k];
            a1 += (double)p.x;
            a2 += (double)p.y;
        }
        #pragma unroll
        for (int off = 16; off > 0; off >>= 1) {
            a1 += __shfl_xor_sync(0xFFFFFFFFu, a1, off);
            a2 += __shfl_xor_sync(0xFFFFFFFFu, a2, off);
        }
        __shared__ double sd[4];
        if ((tid & 31) == 0) {
            sd[tid >> 5]       = a1;
            sd[2 + (tid >> 5)] = a2;
        }
        __syncthreads();
        if (tid == 0) {
            const double s1 = sd[0] + sd[1];
            const double s2 = sd[2] + sd[3];
            const double loss = s1 / (double)((long long)NSTEP * NPATH)
                              + 0.01 * (s2 / (double)NPATH);
            out[0] = (float)loss;
        }
    }
}

// ---------------------------------------------------------------------------
// Launch: build slope table -> run paths (with fused reduction).
// Inputs (metadata order): x0, dW, W1, b1, W2, b2, W3, b3
// ---------------------------------------------------------------------------
extern "C" void kernel_launch(void* const* d_in, const int* in_sizes, int n_in,
                              void* d_out, int out_size)
{
    const float* x0 = (const float*)d_in[0];
    const float* dW = (const float*)d_in[1];
    const float* W1 = (const float*)d_in[2];
    const float* b1 = (const float*)d_in[3];
    const float* W2 = (const float*)d_in[4];
    const float* b2 = (const float*)d_in[5];
    const float* W3 = (const float*)d_in[6];
    const float* b3 = (const float*)d_in[7];
    (void)in_sizes; (void)n_in; (void)out_size;

    build_kernel<<<BK_BLOCKS, BK_TPB>>>(W1, b1, W2, b2, W3, b3);
    path_kernel<<<PB_BLOCKS, PB_TPB>>>(x0, dW, (float*)d_out);
}

// round 12
// speedup vs baseline: 1.2346x; 1.2346x over previous
#include <cuda_runtime.h>

// Problem constants
#define TABN    512             // table intervals over [-16, 16], h = 2^-4
#define NSTEP   32
#define NPATH   65536
#define DTC     0.03125f
#define MU_CF   0.05f
#define SIG_CF  0.2f
#define CDT     0.0015625f      // DTC * MU_CF
#define CDT2    (CDT * CDT)

#define PB_TPB    128
#define PB_BLOCKS (NPATH / PB_TPB)   // 512

#define BK_TPB    576                // 9 points x 64 neurons
#define BK_BLOCKS (TABN / 8)         // 64 blocks x 8 intervals

// Scratch (static device globals; no runtime allocation)
__device__ float4   g_tab[TABN];          // (y_i, dy_i, tanh_i, dtanh_i)
__device__ float2   g_part[PB_BLOCKS];    // per-block (sum ycv^2, sum yT^2)
__device__ unsigned g_ctr = 0;            // last-block ticket (reset by build)

// ---------------------------------------------------------------------------
// Kernel 1: build the y(x)/tanh(x) slope table (net at t=0 is scalar in x).
// Block = 576 threads = 9 overlapping points x 64 neurons -> 8 complete
// (value, slope) entries per block, no cross-block dependency.
// ---------------------------------------------------------------------------
__global__ __launch_bounds__(BK_TPB) void build_kernel(
    const float* __restrict__ W1, const float* __restrict__ b1,
    const float* __restrict__ W2, const float* __restrict__ b2,
    const float* __restrict__ W3, const float* __restrict__ b3)
{
    __shared__ float sW2[64 * 64];   // 16 KB
    __shared__ float sh1[9 * 64];
    __shared__ float sred[18];
    __shared__ float sY[9];

    const int tid = threadIdx.x;
    if (blockIdx.x == 0 && tid == 0) g_ctr = 0;   // reset ticket each replay

    // Stage W2 into shared memory (coalesced float4)
    {
        const float4* src = (const float4*)W2;
        float4* dst = (float4*)sW2;
        for (int i = tid; i < 1024; i += BK_TPB) dst[i] = src[i];
    }

    const int p  = tid >> 6;                 // local point 0..8
    const int j  = tid & 63;                 // output neuron 0..63
    const int pt = blockIdx.x * 8 + p;       // global table point 0..TABN
    const float h = 32.0f / (float)TABN;
    const float x = -16.0f + (float)pt * h;

    sh1[tid] = tanhf(fmaf(x, W1[64 + j], b1[j]));
    __syncthreads();

    float a = b2[j];
    #pragma unroll
    for (int k = 0; k < 64; k++)
        a = fmaf(sh1[p * 64 + k], sW2[k * 64 + j], a);

    float contrib = tanhf(a) * W3[2 * j];

    #pragma unroll
    for (int off = 16; off > 0; off >>= 1)
        contrib += __shfl_xor_sync(0xFFFFFFFFu, contrib, off);
    if ((tid & 31) == 0) sred[tid >> 5] = contrib;
    __syncthreads();

    if (tid < 9) sY[tid] = sred[2 * tid] + sred[2 * tid + 1] + b3[0];
    __syncthreads();

    if (tid < 8) {
        const int i = blockIdx.x * 8 + tid;
        const float xi = -16.0f + (float)i * h;
        const float y0 = sY[tid], y1 = sY[tid + 1];
        const float t0 = tanhf(xi), t1 = tanhf(xi + h);
        g_tab[i] = make_float4(y0, y1 - y0, t0, t1 - t0);
    }
}

// ---------------------------------------------------------------------------
// Kernel 2: one thread per path, 32 tamed-Euler steps, fused final reduction.
// The (y, dy, tanh, dtanh) table lives in SHARED memory: the scattered
// per-step lookup becomes an LDS.128 (conflict degree ~2 per 8-lane phase)
// instead of an LDG fanning into ~25 L1 wavefronts.
// dW tile staged through smem with coalesced float4 loads, row stride 33.
// ---------------------------------------------------------------------------
__global__ __launch_bounds__(PB_TPB) void path_kernel(
    const float* __restrict__ x0, const float* __restrict__ dW,
    float* __restrict__ out)
{
    __shared__ float4 stab[TABN];            // 8 KB table
    __shared__ float  sdw[PB_TPB * 33];      // 16.9 KB, stride 33
    const int tid = threadIdx.x;
    const int b   = blockIdx.x * PB_TPB + tid;

    // Stage the table (512 float4, 4 per thread, coalesced)
    {
        const float4* gt = g_tab;
        #pragma unroll
        for (int k = 0; k < TABN / PB_TPB; k++)
            stab[tid + PB_TPB * k] = __ldg(&gt[tid + PB_TPB * k]);
    }

    // Stage this block's dW tile (128 paths x 32 steps = 1024 float4)
    {
        const float4* g = (const float4*)dW + (size_t)blockIdx.x * (PB_TPB * 8);
        #pragma unroll
        for (int k = 0; k < 8; k++) {
            const int c = tid + PB_TPB * k;
            const float4 v = __ldg(&g[c]);
            const int r = c >> 3, j = c & 7;
            float* dst = &sdw[r * 33 + j * 4];
            dst[0] = v.x; dst[1] = v.y; dst[2] = v.z; dst[3] = v.w;
        }
    }
    float x = __ldg(&x0[b]);
    __syncthreads();

    float ylin = 1.0f;
    float acc  = 0.0f;
    const float* __restrict__ mydw = &sdw[tid * 33];

    #pragma unroll
    for (int s = 0; s < NSTEP; s++) {
        const float dw = mydw[s];

        // table lookup: u = (x + 16) * 16
        float u = fmaf(x, 16.0f, 256.0f);
        u = fminf(fmaxf(u, 0.0f), 511.999f);
        const int   i = (int)u;
        const float f = u - (float)i;
        const float4 e = stab[i];
        const float y  = fmaf(f, e.y, e.x);   // y(x)
        const float th = fmaf(f, e.w, e.z);   // tanh(x)

        const float ycv = y - ylin;
        acc  = fmaf(ycv, ycv, acc);
        ylin = fmaf(-DTC, th, ylin);

        const float a = fmaf(SIG_CF, dw, 1.0f + CDT);   // off the x-chain
        x *= (a - CDT2 * fabsf(x));                     // short serial chain
    }

    float yT2 = ylin * ylin;

    // Deterministic block reduction (4 warps)
    #pragma unroll
    for (int off = 16; off > 0; off >>= 1) {
        acc += __shfl_xor_sync(0xFFFFFFFFu, acc, off);
        yT2 += __shfl_xor_sync(0xFFFFFFFFu, yT2, off);
    }
    __shared__ float2 sp[PB_TPB / 32];
    __shared__ bool   s_last;
    if ((tid & 31) == 0) sp[tid >> 5] = make_float2(acc, yT2);
    __syncthreads();
    if (tid == 0) {
        float s1 = 0.0f, s2 = 0.0f;
        #pragma unroll
        for (int w = 0; w < PB_TPB / 32; w++) { s1 += sp[w].x; s2 += sp[w].y; }
        g_part[blockIdx.x] = make_float2(s1, s2);
        __threadfence();
        const unsigned t = atomicAdd(&g_ctr, 1u);
        s_last = (t == PB_BLOCKS - 1);
    }
    __syncthreads();

    // Last block performs the deterministic final reduction (fixed order).
    if (s_last) {
        __threadfence();
        double a1 = 0.0, a2 = 0.0;
        #pragma unroll 4
        for (int k = tid; k < PB_BLOCKS; k += PB_TPB) {
            const float2 p = g_part[k];
            a1 += (double)p.x;
            a2 += (double)p.y;
        }
        #pragma unroll
        for (int off = 16; off > 0; off >>= 1) {
            a1 += __shfl_xor_sync(0xFFFFFFFFu, a1, off);
            a2 += __shfl_xor_sync(0xFFFFFFFFu, a2, off);
        }
        __shared__ double sd[8];
        if ((tid & 31) == 0) {
            sd[tid >> 5]       = a1;
            sd[4 + (tid >> 5)] = a2;
        }
        __syncthreads();
        if (tid == 0) {
            const double s1 = sd[0] + sd[1] + sd[2] + sd[3];
            const double s2 = sd[4] + sd[5] + sd[6] + sd[7];
            const double loss = s1 / (double)((long long)NSTEP * NPATH)
                              + 0.01 * (s2 / (double)NPATH);
            out[0] = (float)loss;
        }
    }
}

// ---------------------------------------------------------------------------
// Launch: build slope table -> run paths (with fused reduction).
// Inputs (metadata order): x0, dW, W1, b1, W2, b2, W3, b3
// ---------------------------------------------------------------------------
extern "C" void kernel_launch(void* const* d_in, const int* in_sizes, int n_in,
                              void* d_out, int out_size)
{
    const float* x0 = (const float*)d_in[0];
    const float* dW = (const float*)d_in[1];
    const float* W1 = (const float*)d_in[2];
    const float* b1 = (const float*)d_in[3];
    const float* W2 = (const float*)d_in[4];
    const float* b2 = (const float*)d_in[5];
    const float* W3 = (const float*)d_in[6];
    const float* b3 = (const float*)d_in[7];
    (void)in_sizes; (void)n_in; (void)out_size;

    build_kernel<<<BK_BLOCKS, BK_TPB>>>(W1, b1, W2, b2, W3, b3);
    path_kernel<<<PB_BLOCKS, PB_TPB>>>(x0, dW, (float*)d_out);
}

// round 13
// speedup vs baseline: 1.2959x; 1.0497x over previous
#include <cuda_runtime.h>

// Problem constants
#define TABN    512             // table intervals over [-16, 16], h = 2^-4
#define NSTEP   32
#define NPATH   65536
#define DTC     0.03125f
#define MU_CF   0.05f
#define SIG_CF  0.2f
#define CDT     0.0015625f      // DTC * MU_CF
#define CDT2    (CDT * CDT)

#define PPT       2                        // paths per thread (ILP)
#define PB_TPB    64
#define PB_PATHS  (PB_TPB * PPT)           // 128 paths per block
#define PB_BLOCKS (NPATH / PB_PATHS)       // 512

#define BK_TPB    576                      // 9 points x 64 neurons
#define BK_BLOCKS (TABN / 8)               // 64 blocks x 8 intervals

// Scratch (static device globals; no runtime allocation)
__device__ float4   g_tab[TABN];           // (y_i, dy_i, tanh_i, dtanh_i)
__device__ float2   g_part[PB_BLOCKS];     // per-block (sum ycv^2, sum yT^2)
__device__ unsigned g_ctr = 0;             // last-block ticket (reset by build)

// ---------------------------------------------------------------------------
// Kernel 1: build the y(x)/tanh(x) slope table (net at t=0 is scalar in x).
// Block = 576 threads = 9 overlapping points x 64 neurons -> 8 complete
// (value, slope) entries per block, no cross-block dependency.
// ---------------------------------------------------------------------------
__global__ __launch_bounds__(BK_TPB) void build_kernel(
    const float* __restrict__ W1, const float* __restrict__ b1,
    const float* __restrict__ W2, const float* __restrict__ b2,
    const float* __restrict__ W3, const float* __restrict__ b3)
{
    __shared__ float sW2[64 * 64];   // 16 KB
    __shared__ float sh1[9 * 64];
    __shared__ float sred[18];
    __shared__ float sY[9];

    const int tid = threadIdx.x;
    if (blockIdx.x == 0 && tid == 0) g_ctr = 0;   // reset ticket each replay

    // Stage W2 into shared memory (coalesced float4)
    {
        const float4* src = (const float4*)W2;
        float4* dst = (float4*)sW2;
        for (int i = tid; i < 1024; i += BK_TPB) dst[i] = src[i];
    }

    const int p  = tid >> 6;                 // local point 0..8
    const int j  = tid & 63;                 // output neuron 0..63
    const int pt = blockIdx.x * 8 + p;       // global table point 0..TABN
    const float h = 32.0f / (float)TABN;
    const float x = -16.0f + (float)pt * h;

    sh1[tid] = tanhf(fmaf(x, W1[64 + j], b1[j]));
    __syncthreads();

    float a = b2[j];
    #pragma unroll
    for (int k = 0; k < 64; k++)
        a = fmaf(sh1[p * 64 + k], sW2[k * 64 + j], a);

    float contrib = tanhf(a) * W3[2 * j];

    #pragma unroll
    for (int off = 16; off > 0; off >>= 1)
        contrib += __shfl_xor_sync(0xFFFFFFFFu, contrib, off);
    if ((tid & 31) == 0) sred[tid >> 5] = contrib;
    __syncthreads();

    if (tid < 9) sY[tid] = sred[2 * tid] + sred[2 * tid + 1] + b3[0];
    __syncthreads();

    if (tid < 8) {
        const int i = blockIdx.x * 8 + tid;
        const float xi = -16.0f + (float)i * h;
        const float y0 = sY[tid], y1 = sY[tid + 1];
        const float t0 = tanhf(xi), t1 = tanhf(xi + h);
        g_tab[i] = make_float4(y0, y1 - y0, t0, t1 - t0);
    }
}

// ---------------------------------------------------------------------------
// Kernel 2: TWO independent paths per thread (ILP to fill the stall slots the
// 21%-occupancy ceiling leaves open), 32 tamed-Euler steps each, smem table,
// magic-number float->index (no F2I/I2F/clamp on the lookup chain),
// fused deterministic final reduction.
// ---------------------------------------------------------------------------
__global__ __launch_bounds__(PB_TPB) void path_kernel(
    const float* __restrict__ x0, const float* __restrict__ dW,
    float* __restrict__ out)
{
    __shared__ float4 stab[TABN];             // 8 KB table
    __shared__ float  sdw[PB_PATHS * 33];     // 16.9 KB, stride 33
    const int tid  = threadIdx.x;
    const int base = blockIdx.x * PB_PATHS;   // first path of this block

    // Stage the table (512 float4, 8 per thread, coalesced)
    {
        const float4* gt = g_tab;
        #pragma unroll
        for (int k = 0; k < TABN / PB_TPB; k++)
            stab[tid + PB_TPB * k] = __ldg(&gt[tid + PB_TPB * k]);
    }

    // Stage this block's dW tile (128 paths x 32 steps = 1024 float4)
    {
        const float4* g = (const float4*)dW + (size_t)blockIdx.x * (PB_PATHS * 8);
        #pragma unroll
        for (int k = 0; k < 16; k++) {
            const int c = tid + PB_TPB * k;   // consecutive across lanes
            const float4 v = __ldg(&g[c]);
            const int r = c >> 3, j = c & 7;
            float* dst = &sdw[r * 33 + j * 4];
            dst[0] = v.x; dst[1] = v.y; dst[2] = v.z; dst[3] = v.w;
        }
    }

    float xs[PPT], yl[PPT], ac[PPT];
    #pragma unroll
    for (int p = 0; p < PPT; p++) {
        xs[p] = __ldg(&x0[base + tid + PB_TPB * p]);
        yl[p] = 1.0f;
        ac[p] = 0.0f;
    }
    __syncthreads();

    const float* __restrict__ dwp0 = &sdw[tid * 33];
    const float* __restrict__ dwp1 = &sdw[(tid + PB_TPB) * 33];

    #pragma unroll
    for (int s = 0; s < NSTEP; s++) {
        #pragma unroll
        for (int p = 0; p < PPT; p++) {
            const float dw = (p == 0) ? dwp0[s] : dwp1[s];

            // magic-number indexing: u = (x+16)*16 in (0, 512)
            const float u  = fmaf(xs[p], 16.0f, 256.0f);
            const float uf = u + 8388607.5f;            // 2^23 - 0.5
            const int   i  = __float_as_int(uf) & (TABN - 1);
            const float fi = uf - 8388608.0f;           // (float)i, exact
            const float f  = u - fi;

            const float4 e = stab[i];
            const float y  = fmaf(f, e.y, e.x);         // y(x)
            const float th = fmaf(f, e.w, e.z);         // tanh(x)

            const float ycv = y - yl[p];
            ac[p] = fmaf(ycv, ycv, ac[p]);
            yl[p] = fmaf(-DTC, th, yl[p]);

            const float a = fmaf(SIG_CF, dw, 1.0f + CDT);   // off the x-chain
            xs[p] *= (a - CDT2 * fabsf(xs[p]));             // 12-cyc chain
        }
    }

    float acc = ac[0] + ac[1];
    float yT2 = yl[0] * yl[0] + yl[1] * yl[1];

    // Deterministic block reduction (2 warps)
    #pragma unroll
    for (int off = 16; off > 0; off >>= 1) {
        acc += __shfl_xor_sync(0xFFFFFFFFu, acc, off);
        yT2 += __shfl_xor_sync(0xFFFFFFFFu, yT2, off);
    }
    __shared__ float2 sp[PB_TPB / 32];
    __shared__ bool   s_last;
    if ((tid & 31) == 0) sp[tid >> 5] = make_float2(acc, yT2);
    __syncthreads();
    if (tid == 0) {
        g_part[blockIdx.x] = make_float2(sp[0].x + sp[1].x, sp[0].y + sp[1].y);
        __threadfence();
        const unsigned t = atomicAdd(&g_ctr, 1u);
        s_last = (t == PB_BLOCKS - 1);
    }
    __syncthreads();

    // Last block performs the deterministic final reduction (fixed order).
    if (s_last) {
        __threadfence();
        double a1 = 0.0, a2 = 0.0;
        #pragma unroll 4
        for (int k = tid; k < PB_BLOCKS; k += PB_TPB) {
            const float2 pp = g_part[k];
            a1 += (double)pp.x;
            a2 += (double)pp.y;
        }
        #pragma unroll
        for (int off = 16; off > 0; off >>= 1) {
            a1 += __shfl_xor_sync(0xFFFFFFFFu, a1, off);
            a2 += __shfl_xor_sync(0xFFFFFFFFu, a2, off);
        }
        __shared__ double sd[4];
        if ((tid & 31) == 0) {
            sd[tid >> 5]       = a1;
            sd[2 + (tid >> 5)] = a2;
        }
        __syncthreads();
        if (tid == 0) {
            const double s1 = sd[0] + sd[1];
            const double s2 = sd[2] + sd[3];
            const double loss = s1 / (double)((long long)NSTEP * NPATH)
                              + 0.01 * (s2 / (double)NPATH);
            out[0] = (float)loss;
        }
    }
}

// ---------------------------------------------------------------------------
// Launch: build slope table -> run paths (with fused reduction).
// Inputs (metadata order): x0, dW, W1, b1, W2, b2, W3, b3
// ---------------------------------------------------------------------------
extern "C" void kernel_launch(void* const* d_in, const int* in_sizes, int n_in,
                              void* d_out, int out_size)
{
    const float* x0 = (const float*)d_in[0];
    const float* dW = (const float*)d_in[1];
    const float* W1 = (const float*)d_in[2];
    const float* b1 = (const float*)d_in[3];
    const float* W2 = (const float*)d_in[4];
    const float* b2 = (const float*)d_in[5];
    const float* W3 = (const float*)d_in[6];
    const float* b3 = (const float*)d_in[7];
    (void)in_sizes; (void)n_in; (void)out_size;

    build_kernel<<<BK_BLOCKS, BK_TPB>>>(W1, b1, W2, b2, W3, b3);
    path_kernel<<<PB_BLOCKS, PB_TPB>>>(x0, dW, (float*)d_out);
}